// round 6
// baseline (speedup 1.0000x reference)
#include <cuda_runtime.h>
#include <math.h>
#include <cstdint>

// Problem constants
#define BB 2
#define SS 2048
#define EE 2048
#define HH_ 16
#define DD 128
#define E3 (3*EE)

// Scratch (allocation-free rule: __device__ globals)
__device__ float g_qkv[(long)BB*SS*E3];        //  96 MB
__device__ float g_ctx[(long)BB*SS*EE];        //  32 MB

__device__ __forceinline__ uint32_t f2tf(float f) {
    uint32_t r; asm("cvt.rna.tf32.f32 %0, %1;" : "=r"(r) : "f"(f)); return r;
}
__device__ __forceinline__ float tfround(float f) {
    return __uint_as_float(f2tf(f));
}
__device__ __forceinline__ void mma8(float* d, const uint32_t* a, const uint32_t* b) {
    asm volatile("mma.sync.aligned.m16n8k8.row.col.f32.tf32.tf32.f32 "
        "{%0,%1,%2,%3}, {%4,%5,%6,%7}, {%8,%9}, {%0,%1,%2,%3};"
        : "+f"(d[0]), "+f"(d[1]), "+f"(d[2]), "+f"(d[3])
        : "r"(a[0]), "r"(a[1]), "r"(a[2]), "r"(a[3]), "r"(b[0]), "r"(b[1]));
}
__device__ __forceinline__ uint32_t smem_u32(const void* p) {
    uint32_t a;
    asm("{ .reg .u64 t; cvta.to.shared.u64 t, %1; cvt.u32.u64 %0, t; }"
        : "=r"(a) : "l"(p));
    return a;
}
#define CP_ASYNC16(dst, src) \
    asm volatile("cp.async.ca.shared.global [%0], [%1], 16;" :: "r"(dst), "l"(src))
#define CP_COMMIT() asm volatile("cp.async.commit_group;" ::: "memory")
#define CP_WAIT(n)  asm volatile("cp.async.wait_group %0;" :: "n"(n) : "memory")

// ===========================================================================
// Pipelined GEMM (TRANSB): C[m,n]= sum_k A[m,k]*B[n,k] (+bias)
// CTA tile 128x256, 8 warps (2x4), warp tile 64x64, BK=32, 3-stage cp.async.
// ===========================================================================
#define BM2 128
#define BN2 256
#define BKT 32
#define LDP 36
#define A_ST (128*LDP)
#define B_ST (256*LDP)
#define ST_U (A_ST + B_ST)
#define SMEM2 (3*ST_U*4)           // 165888 bytes

template<bool BIAS>
__global__ __launch_bounds__(256)
void tgemm2(const float* __restrict__ gA, const float* __restrict__ gB,
            float* __restrict__ gC, const float* __restrict__ bias,
            int K, int lda, int ldb, int ldc)
{
    extern __shared__ float smf[];
    const float* A = gA;
    const float* B = gB;
    float*       C = gC;

    int m0 = blockIdx.y * BM2;
    int n0 = blockIdx.x * BN2;
    int niter = K / BKT;

    int tid  = threadIdx.x;
    int wid  = tid >> 5;
    int lane = tid & 31;
    int wm = wid & 1;
    int wn = wid >> 1;
    int gq = lane >> 2;
    int tg = lane & 3;

    float acc[4][8][4];
    #pragma unroll
    for (int mt = 0; mt < 4; mt++)
        #pragma unroll
        for (int nt = 0; nt < 8; nt++)
            #pragma unroll
            for (int r = 0; r < 4; r++) acc[mt][nt][r] = 0.f;

    auto issue = [&](int it) {
        int k0 = it * BKT;
        float* As = smf + (it % 3) * ST_U;
        float* Bs = As + A_ST;
        const float* Ab = A + (long)m0 * lda + k0;
        #pragma unroll
        for (int p = 0; p < 4; p++) {
            int idx = p * 256 + tid;
            int r = idx >> 3, c4 = (idx & 7) << 2;
            CP_ASYNC16(smem_u32(As + r * LDP + c4), Ab + (long)r * lda + c4);
        }
        const float* Bb = B + (long)n0 * ldb + k0;
        #pragma unroll
        for (int p = 0; p < 8; p++) {
            int idx = p * 256 + tid;
            int r = idx >> 3, c4 = (idx & 7) << 2;
            CP_ASYNC16(smem_u32(Bs + r * LDP + c4), Bb + (long)r * ldb + c4);
        }
        CP_COMMIT();
    };

    auto compute = [&](int s) {
        const float* As = smf + s * ST_U;
        const float* Bs = As + A_ST;
        #pragma unroll
        for (int ks = 0; ks < 4; ks++) {
            int kc = ks * 8;
            uint32_t a[4][4], b[8][2];
            #pragma unroll
            for (int mt = 0; mt < 4; mt++) {
                const float* p0 = As + (wm*64 + mt*16 + gq) * LDP + kc + tg;
                const float* p1 = p0 + 8 * LDP;
                a[mt][0] = f2tf(p0[0]); a[mt][2] = f2tf(p0[4]);
                a[mt][1] = f2tf(p1[0]); a[mt][3] = f2tf(p1[4]);
            }
            #pragma unroll
            for (int nt = 0; nt < 8; nt++) {
                const float* pb = Bs + (wn*64 + nt*8 + gq) * LDP + kc + tg;
                b[nt][0] = f2tf(pb[0]); b[nt][1] = f2tf(pb[4]);
            }
            #pragma unroll
            for (int mt = 0; mt < 4; mt++)
                #pragma unroll
                for (int nt = 0; nt < 8; nt++)
                    mma8(acc[mt][nt], a[mt], b[nt]);
        }
    };

    issue(0);
    if (niter > 1) issue(1);
    for (int it = 0; it < niter; ++it) {
        if (it + 1 < niter) CP_WAIT(1); else CP_WAIT(0);
        __syncthreads();
        if (it + 2 < niter) issue(it + 2);
        compute(it % 3);
        // no trailing sync: top-of-loop barrier orders compute(it) before
        // issue(it+3) can overwrite this stage (3-stage ring)
    }

    #pragma unroll
    for (int mt = 0; mt < 4; mt++) {
        int row = m0 + wm*64 + mt*16 + gq;
        #pragma unroll
        for (int nt = 0; nt < 8; nt++) {
            int col = n0 + wn*64 + nt*8 + 2*tg;
            float b0 = 0.f, b1 = 0.f;
            if (BIAS) { b0 = bias[col]; b1 = bias[col + 1]; }
            float2 v0, v1;
            v0.x = acc[mt][nt][0] + b0; v0.y = acc[mt][nt][1] + b1;
            v1.x = acc[mt][nt][2] + b0; v1.y = acc[mt][nt][3] + b1;
            *(float2*)(C + (long)row * ldc + col)       = v0;
            *(float2*)(C + (long)(row + 8) * ldc + col) = v1;
        }
    }
}

// ===========================================================================
// Flash attention. Per CTA: one 128-row q-tile of one (b,h).
// q,k,v are PRE-ROUNDED to tf32 (and q pre-scaled) by rope_k, so fragments
// are raw 32-bit loads. K double-buffered (next-K prefetch overlaps compute).
// Smem u32: Q[128][132] | K0[64][132] | K1[64][132] | V[64][136] | P[128][68]
//          = 51200 u32 = 204800 bytes
// ===========================================================================
#define FQ_LD 132
#define FV_LD 136
#define FP_LD 68
#define FA_OFF_K0 (128*FQ_LD)              // 16896
#define FA_OFF_K1 (FA_OFF_K0 + 64*FQ_LD)   // 25344
#define FA_OFF_V  (FA_OFF_K1 + 64*FQ_LD)   // 33792
#define FA_OFF_P  (FA_OFF_V  + 64*FV_LD)   // 42496
#define FA_SMEM   ((FA_OFF_P + 128*FP_LD)*4)

__global__ __launch_bounds__(256)
void fa_k(const float* __restrict__ qkv, float* __restrict__ ctx)
{
    extern __shared__ uint32_t sm[];
    uint32_t* Qs = sm;
    uint32_t* Vu = sm + FA_OFF_V;
    uint32_t* Ps = sm + FA_OFF_P;

    int qt = gridDim.x - 1 - blockIdx.x;       // heavy tiles first
    int bh = blockIdx.y;
    int b = bh >> 4, h = bh & 15;
    const float* qb = qkv + (long)b*SS*E3 + (long)h*DD;

    int tid = threadIdx.x, wid = tid >> 5, lane = tid & 31;
    int gq = lane >> 2, tg = lane & 3;

    auto issueK = [&](int kt) {
        uint32_t* Kd = sm + ((kt & 1) ? FA_OFF_K1 : FA_OFF_K0);
        const float* Kg = qb + EE + (long)(kt*64)*E3;
        #pragma unroll
        for (int p = 0; p < 8; p++) {
            int idx = p*256 + tid;
            int r = idx >> 5, c4 = (idx & 31) << 2;
            CP_ASYNC16(smem_u32(Kd + r*FQ_LD + c4), Kg + (long)r*E3 + c4);
        }
    };
    auto issueV = [&](int kt) {
        const float* Vg = qb + 2*EE + (long)(kt*64)*E3;
        #pragma unroll
        for (int p = 0; p < 8; p++) {
            int idx = p*256 + tid;
            int r = idx >> 5, c4 = (idx & 31) << 2;
            CP_ASYNC16(smem_u32(Vu + r*FV_LD + c4), Vg + (long)r*E3 + c4);
        }
    };

    // Q tile via cp.async (already tf32 bits)
    {
        const float* Qg = qb + (long)(qt*128)*E3;
        #pragma unroll
        for (int p = 0; p < 16; p++) {
            int idx = p*256 + tid;
            int r = idx >> 5, c4 = (idx & 31) << 2;
            CP_ASYNC16(smem_u32(Qs + r*FQ_LD + c4), Qg + (long)r*E3 + c4);
        }
    }
    issueK(0); issueV(0); CP_COMMIT();

    float o[16][4];
    #pragma unroll
    for (int nt = 0; nt < 16; nt++)
        #pragma unroll
        for (int r = 0; r < 4; r++) o[nt][r] = 0.f;
    float m0 = -1e30f, m1 = -1e30f, l0 = 0.f, l1 = 0.f;

    int rowg0 = qt*128 + wid*16 + gq;
    int rowg1 = rowg0 + 8;
    int nkt = 2*(qt + 1);

    for (int kt = 0; kt < nkt; kt++) {
        CP_WAIT(0);
        __syncthreads();                    // K(kt), V(kt), (Q) ready
        if (kt + 1 < nkt) { issueK(kt + 1); CP_COMMIT(); }  // prefetch next K

        const uint32_t* Ku = sm + ((kt & 1) ? FA_OFF_K1 : FA_OFF_K0);

        // ---- S = Q K^T (warp: 16 rows x 64 cols), raw tf32 fragments ----
        float s[8][4];
        #pragma unroll
        for (int nt = 0; nt < 8; nt++)
            #pragma unroll
            for (int r = 0; r < 4; r++) s[nt][r] = 0.f;

        #pragma unroll
        for (int ks = 0; ks < 16; ks++) {
            int kc = ks*8;
            uint32_t a[4];
            const uint32_t* p0 = Qs + (wid*16 + gq)*FQ_LD + kc + tg;
            const uint32_t* p1 = p0 + 8*FQ_LD;
            a[0] = p0[0]; a[1] = p1[0]; a[2] = p0[4]; a[3] = p1[4];
            #pragma unroll
            for (int nt = 0; nt < 8; nt++) {
                const uint32_t* pb = Ku + (nt*8 + gq)*FQ_LD + kc + tg;
                uint32_t bb[2] = { pb[0], pb[4] };
                mma8(s[nt], a, bb);
            }
        }

        // ---- causal mask (q pre-scaled; no scale mul needed) ----
        if (kt >= 2*qt) {
            #pragma unroll
            for (int nt = 0; nt < 8; nt++) {
                int col = kt*64 + nt*8 + 2*tg;
                if (col   > rowg0) s[nt][0] = -1e30f;
                if (col+1 > rowg0) s[nt][1] = -1e30f;
                if (col   > rowg1) s[nt][2] = -1e30f;
                if (col+1 > rowg1) s[nt][3] = -1e30f;
            }
        }

        // ---- online softmax ----
        float mt0 = -1e30f, mt1 = -1e30f;
        #pragma unroll
        for (int nt = 0; nt < 8; nt++) {
            mt0 = fmaxf(mt0, fmaxf(s[nt][0], s[nt][1]));
            mt1 = fmaxf(mt1, fmaxf(s[nt][2], s[nt][3]));
        }
        mt0 = fmaxf(mt0, __shfl_xor_sync(0xffffffffu, mt0, 1));
        mt0 = fmaxf(mt0, __shfl_xor_sync(0xffffffffu, mt0, 2));
        mt1 = fmaxf(mt1, __shfl_xor_sync(0xffffffffu, mt1, 1));
        mt1 = fmaxf(mt1, __shfl_xor_sync(0xffffffffu, mt1, 2));

        float mn0 = fmaxf(m0, mt0), mn1 = fmaxf(m1, mt1);
        float c0 = __expf(m0 - mn0), c1 = __expf(m1 - mn1);

        float sum0 = 0.f, sum1 = 0.f;
        #pragma unroll
        for (int nt = 0; nt < 8; nt++) {
            s[nt][0] = __expf(s[nt][0] - mn0);
            s[nt][1] = __expf(s[nt][1] - mn0);
            s[nt][2] = __expf(s[nt][2] - mn1);
            s[nt][3] = __expf(s[nt][3] - mn1);
            sum0 += s[nt][0] + s[nt][1];
            sum1 += s[nt][2] + s[nt][3];
        }
        sum0 += __shfl_xor_sync(0xffffffffu, sum0, 1);
        sum0 += __shfl_xor_sync(0xffffffffu, sum0, 2);
        sum1 += __shfl_xor_sync(0xffffffffu, sum1, 1);
        sum1 += __shfl_xor_sync(0xffffffffu, sum1, 2);

        l0 = l0*c0 + sum0;  l1 = l1*c1 + sum1;
        m0 = mn0;           m1 = mn1;

        #pragma unroll
        for (int nt = 0; nt < 16; nt++) {
            o[nt][0] *= c0; o[nt][1] *= c0;
            o[nt][2] *= c1; o[nt][3] *= c1;
        }

        // ---- P (tf32) -> warp-private smem ----
        #pragma unroll
        for (int nt = 0; nt < 8; nt++) {
            int cb = nt*8 + 2*tg;
            uint2 v0 = make_uint2(f2tf(s[nt][0]), f2tf(s[nt][1]));
            uint2 v1 = make_uint2(f2tf(s[nt][2]), f2tf(s[nt][3]));
            *(uint2*)&Ps[(wid*16 + gq    )*FP_LD + cb] = v0;
            *(uint2*)&Ps[(wid*16 + gq + 8)*FP_LD + cb] = v1;
        }
        __syncwarp();

        // ---- O += P @ V (raw tf32 V fragments) ----
        #pragma unroll
        for (int ks = 0; ks < 8; ks++) {
            int kc = ks*8;
            uint32_t a[4];
            const uint32_t* p0 = Ps + (wid*16 + gq)*FP_LD + kc + tg;
            const uint32_t* p1 = p0 + 8*FP_LD;
            a[0] = p0[0]; a[1] = p1[0]; a[2] = p0[4]; a[3] = p1[4];
            #pragma unroll
            for (int nt = 0; nt < 16; nt++) {
                const uint32_t* pv = Vu + (kc + tg)*FV_LD + nt*8 + gq;
                uint32_t bb[2] = { pv[0], pv[4*FV_LD] };
                mma8(o[nt], a, bb);
            }
        }
        __syncthreads();                    // all warps done with V (and P)
        if (kt + 1 < nkt) { issueV(kt + 1); CP_COMMIT(); }
    }

    // ---- normalize + store ----
    float i0 = 1.f/l0, i1 = 1.f/l1;
    float* cb0 = ctx + (long)b*SS*EE + (long)rowg0*EE + h*DD;
    float* cb1 = cb0 + 8*EE;
    #pragma unroll
    for (int nt = 0; nt < 16; nt++) {
        int col = nt*8 + 2*tg;
        float2 v0 = make_float2(o[nt][0]*i0, o[nt][1]*i0);
        float2 v1 = make_float2(o[nt][2]*i1, o[nt][3]*i1);
        *(float2*)(cb0 + col) = v0;
        *(float2*)(cb1 + col) = v1;
    }
}

// ---------------------------------------------------------------------------
// RoPE in-place on q,k; also pre-scales q by 1/sqrt(D) and rounds q,k,v
// to tf32 bit patterns so the FA kernel can feed MMA fragments raw.
// ---------------------------------------------------------------------------
__global__ __launch_bounds__(256)
void rope_k(float* __restrict__ qkv)
{
    long t = (long)blockIdx.x * blockDim.x + threadIdx.x;
    int j = (int)(t & 63);
    int h = (int)((t >> 6) & (HH_-1));
    long bs = t >> 10;
    int s = (int)(bs & (SS-1));

    const float scale = 0.08838834764831845f;  // 1/sqrt(128)
    float inv = powf(10000.f, -((float)(2*j)) * (1.f/128.f));
    float fr  = (float)s * inv;
    float c, sn;
    sincosf(fr, &sn, &c);

    float* q = qkv + bs*(long)E3 + (long)h*DD;
    float q1 = q[j], q2 = q[j+64];
    q[j]    = tfround((q1*c - q2*sn) * scale);
    q[j+64] = tfround((q1*sn + q2*c) * scale);

    float* k = q + EE;
    float k1 = k[j], k2 = k[j+64];
    k[j]    = tfround(k1*c - k2*sn);
    k[j+64] = tfround(k1*sn + k2*c);

    float* v = k + EE;
    v[j]    = tfround(v[j]);
    v[j+64] = tfround(v[j+64]);
}

// ---------------------------------------------------------------------------
extern "C" void kernel_launch(void* const* d_in, const int* in_sizes, int n_in,
                              void* d_out, int out_size)
{
    const float* x      = (const float*)d_in[0];
    const float* wqkv_w = (const float*)d_in[1];
    const float* wqkv_b = (const float*)d_in[2];
    const float* out_w  = (const float*)d_in[3];
    const float* out_b  = (const float*)d_in[4];
    float*       out    = (float*)d_out;

    float *qkv, *ctx;
    cudaGetSymbolAddress((void**)&qkv, g_qkv);
    cudaGetSymbolAddress((void**)&ctx, g_ctx);

    cudaFuncSetAttribute(tgemm2<true>, cudaFuncAttributeMaxDynamicSharedMemorySize, SMEM2);
    cudaFuncSetAttribute(fa_k,         cudaFuncAttributeMaxDynamicSharedMemorySize, FA_SMEM);

    const int Mx = BB*SS;             // 4096

    // 1) QKV projection: [4096,2048] @ [6144,2048]^T + bias
    {
        dim3 g(E3/BN2, Mx/BM2, 1);
        tgemm2<true><<<g,256,SMEM2>>>(x, wqkv_w, qkv, wqkv_b, EE, EE, EE, E3);
    }
    // 2) RoPE + tf32 pre-round + q pre-scale
    {
        long total = (long)BB*SS*HH_*64;
        rope_k<<<(unsigned)(total/256), 256>>>(qkv);
    }
    // 3) fused flash attention -> ctx
    {
        dim3 g(SS/128, BB*HH_);
        fa_k<<<g,256,FA_SMEM>>>(qkv, ctx);
    }
    // 4) output projection
    {
        dim3 g(EE/BN2, Mx/BM2, 1);
        tgemm2<true><<<g,256,SMEM2>>>(ctx, out_w, out, out_b, EE, EE, EE, EE);
    }
}

// round 7
// speedup vs baseline: 1.0729x; 1.0729x over previous
#include <cuda_runtime.h>
#include <math.h>
#include <cstdint>

// Problem constants
#define BB 2
#define SS 2048
#define EE 2048
#define HH_ 16
#define DD 128
#define E3 (3*EE)

// Scratch (allocation-free rule: __device__ globals)
__device__ float g_qkv[(long)BB*SS*E3];        //  96 MB
__device__ float g_ctx[(long)BB*SS*EE];        //  32 MB
__device__ float g_xr [(long)BB*SS*EE];        //  32 MB (tf32-rounded x)
__device__ float g_w1r[(long)E3*EE];           //  50 MB (tf32-rounded wqkv_w)
__device__ float g_w2r[(long)EE*EE];           //  16 MB (tf32-rounded out_w)

__device__ __forceinline__ uint32_t f2tf(float f) {
    uint32_t r; asm("cvt.rna.tf32.f32 %0, %1;" : "=r"(r) : "f"(f)); return r;
}
__device__ __forceinline__ float tfround(float f) {
    return __uint_as_float(f2tf(f));
}
__device__ __forceinline__ void mma8(float* d, const uint32_t* a, const uint32_t* b) {
    asm volatile("mma.sync.aligned.m16n8k8.row.col.f32.tf32.tf32.f32 "
        "{%0,%1,%2,%3}, {%4,%5,%6,%7}, {%8,%9}, {%0,%1,%2,%3};"
        : "+f"(d[0]), "+f"(d[1]), "+f"(d[2]), "+f"(d[3])
        : "r"(a[0]), "r"(a[1]), "r"(a[2]), "r"(a[3]), "r"(b[0]), "r"(b[1]));
}
__device__ __forceinline__ void ldsm4(uint32_t* r, uint32_t addr) {
    asm volatile("ldmatrix.sync.aligned.m8n8.x4.shared.b16 {%0,%1,%2,%3}, [%4];"
        : "=r"(r[0]), "=r"(r[1]), "=r"(r[2]), "=r"(r[3]) : "r"(addr));
}
__device__ __forceinline__ uint32_t smem_u32(const void* p) {
    uint32_t a;
    asm("{ .reg .u64 t; cvta.to.shared.u64 t, %1; cvt.u32.u64 %0, t; }"
        : "=r"(a) : "l"(p));
    return a;
}
#define CP_ASYNC16(dst, src) \
    asm volatile("cp.async.ca.shared.global [%0], [%1], 16;" :: "r"(dst), "l"(src))
#define CP_COMMIT() asm volatile("cp.async.commit_group;" ::: "memory")
#define CP_WAIT(n)  asm volatile("cp.async.wait_group %0;" :: "n"(n) : "memory")

// ---------------------------------------------------------------------------
// tf32 round-copy (x, weights) so GEMM fragments can be fed raw.
// ---------------------------------------------------------------------------
__global__ __launch_bounds__(256)
void tfcopy_k(const float* __restrict__ in, float* __restrict__ out)
{
    long i = ((long)blockIdx.x*256 + threadIdx.x) * 4;
    float4 v = *(const float4*)(in + i);
    v.x = tfround(v.x); v.y = tfround(v.y);
    v.z = tfround(v.z); v.w = tfround(v.w);
    *(float4*)(out + i) = v;
}

// ===========================================================================
// Pipelined GEMM (TRANSB): C[m,n]= sum_k A[m,k]*B[n,k] (+bias)
// CTA 128x256, 8 warps (2x4), warp 64x64, BK=32, 3-stage cp.async, ldmatrix.
// Inputs MUST be pre-rounded to tf32 bit patterns.
// ===========================================================================
#define BM2 128
#define BN2 256
#define BKT 32
#define LDP 36
#define A_ST (128*LDP)
#define B_ST (256*LDP)
#define ST_U (A_ST + B_ST)
#define SMEM2 (3*ST_U*4)           // 165888 bytes

template<bool BIAS>
__global__ __launch_bounds__(256)
void tgemm2(const float* __restrict__ gA, const float* __restrict__ gB,
            float* __restrict__ gC, const float* __restrict__ bias,
            int K, int lda, int ldb, int ldc)
{
    extern __shared__ float smf[];
    int m0 = blockIdx.y * BM2;
    int n0 = blockIdx.x * BN2;
    int niter = K / BKT;

    int tid  = threadIdx.x;
    int wid  = tid >> 5;
    int lane = tid & 31;
    int wm = wid & 1;
    int wn = wid >> 1;
    int gq = lane >> 2;
    int tg = lane & 3;

    // ldmatrix per-lane offsets (A-style and B-style tile layouts)
    int a_row = (lane & 7) + ((lane >> 3) & 1) * 8;
    int a_col = (lane >> 4) * 4;
    int b_row = (lane & 7) + (lane >> 4) * 8;
    int b_col = ((lane >> 3) & 1) * 4;
    uint32_t smbase = smem_u32(smf);
    uint32_t aoff = ((wm*64 + a_row) * LDP + a_col) * 4;
    uint32_t boff = (uint32_t)(A_ST*4) + ((wn*64 + b_row) * LDP + b_col) * 4;

    float acc[4][8][4];
    #pragma unroll
    for (int mt = 0; mt < 4; mt++)
        #pragma unroll
        for (int nt = 0; nt < 8; nt++)
            #pragma unroll
            for (int r = 0; r < 4; r++) acc[mt][nt][r] = 0.f;

    auto issue = [&](int it) {
        int k0 = it * BKT;
        float* As = smf + (it % 3) * ST_U;
        float* Bs = As + A_ST;
        const float* Ab = gA + (long)m0 * lda + k0;
        #pragma unroll
        for (int p = 0; p < 4; p++) {
            int idx = p * 256 + tid;
            int r = idx >> 3, c4 = (idx & 7) << 2;
            CP_ASYNC16(smem_u32(As + r * LDP + c4), Ab + (long)r * lda + c4);
        }
        const float* Bb = gB + (long)n0 * ldb + k0;
        #pragma unroll
        for (int p = 0; p < 8; p++) {
            int idx = p * 256 + tid;
            int r = idx >> 3, c4 = (idx & 7) << 2;
            CP_ASYNC16(smem_u32(Bs + r * LDP + c4), Bb + (long)r * ldb + c4);
        }
        CP_COMMIT();
    };

    auto compute = [&](int s) {
        uint32_t a_base = smbase + s*(ST_U*4) + aoff;
        uint32_t b_base = smbase + s*(ST_U*4) + boff;
        #pragma unroll
        for (int ks = 0; ks < 4; ks++) {
            uint32_t kc4 = ks * 32;
            uint32_t a[4][4], b[4][4];
            #pragma unroll
            for (int mt = 0; mt < 4; mt++)
                ldsm4(a[mt], a_base + mt*(16*LDP*4) + kc4);
            #pragma unroll
            for (int np = 0; np < 4; np++)
                ldsm4(b[np], b_base + np*(16*LDP*4) + kc4);
            #pragma unroll
            for (int mt = 0; mt < 4; mt++)
                #pragma unroll
                for (int np = 0; np < 4; np++) {
                    mma8(acc[mt][2*np],   a[mt], &b[np][0]);
                    mma8(acc[mt][2*np+1], a[mt], &b[np][2]);
                }
        }
    };

    issue(0);
    if (niter > 1) issue(1);
    for (int it = 0; it < niter; ++it) {
        if (it + 1 < niter) CP_WAIT(1); else CP_WAIT(0);
        __syncthreads();
        if (it + 2 < niter) issue(it + 2);
        compute(it % 3);
    }

    #pragma unroll
    for (int mt = 0; mt < 4; mt++) {
        int row = m0 + wm*64 + mt*16 + gq;
        #pragma unroll
        for (int nt = 0; nt < 8; nt++) {
            int col = n0 + wn*64 + nt*8 + 2*tg;
            float b0 = 0.f, b1 = 0.f;
            if (BIAS) { b0 = bias[col]; b1 = bias[col + 1]; }
            float2 v0, v1;
            v0.x = acc[mt][nt][0] + b0; v0.y = acc[mt][nt][1] + b1;
            v1.x = acc[mt][nt][2] + b0; v1.y = acc[mt][nt][3] + b1;
            *(float2*)(gC + (long)row * ldc + col)       = v0;
            *(float2*)(gC + (long)(row + 8) * ldc + col) = v1;
        }
    }
}

// ===========================================================================
// Flash attention. Per CTA: one 128-row q-tile of one (b,h).
// q,k,v pre-rounded tf32 (q pre-scaled). Q/K/P fragments via ldmatrix.
// Smem u32: Q[128][132] | K0[64][132] | K1[64][132] | V[64][136] | P[128][68]
// ===========================================================================
#define FQ_LD 132
#define FV_LD 136
#define FP_LD 68
#define FA_OFF_K0 (128*FQ_LD)
#define FA_OFF_K1 (FA_OFF_K0 + 64*FQ_LD)
#define FA_OFF_V  (FA_OFF_K1 + 64*FQ_LD)
#define FA_OFF_P  (FA_OFF_V  + 64*FV_LD)
#define FA_SMEM   ((FA_OFF_P + 128*FP_LD)*4)

__global__ __launch_bounds__(256)
void fa_k(const float* __restrict__ qkv, float* __restrict__ ctx)
{
    extern __shared__ uint32_t sm[];
    uint32_t* Qs = sm;
    uint32_t* Vu = sm + FA_OFF_V;
    uint32_t* Ps = sm + FA_OFF_P;

    int qt = gridDim.x - 1 - blockIdx.x;       // heavy tiles first
    int bh = blockIdx.y;
    int b = bh >> 4, h = bh & 15;
    const float* qb = qkv + (long)b*SS*E3 + (long)h*DD;

    int tid = threadIdx.x, wid = tid >> 5, lane = tid & 31;
    int gq = lane >> 2, tg = lane & 3;

    int a_row = (lane & 7) + ((lane >> 3) & 1) * 8;
    int a_col = (lane >> 4) * 4;
    int b_row = (lane & 7) + (lane >> 4) * 8;
    int b_col = ((lane >> 3) & 1) * 4;
    uint32_t smbase = smem_u32(sm);
    uint32_t qa_base = smbase + (((wid*16 + a_row)*FQ_LD + a_col)) * 4;
    uint32_t kb_off  = (b_row*FQ_LD + b_col) * 4;
    uint32_t pa_base = smbase + (uint32_t)(FA_OFF_P*4)
                     + ((wid*16 + a_row)*FP_LD + a_col) * 4;

    auto issueK = [&](int kt) {
        uint32_t* Kd = sm + ((kt & 1) ? FA_OFF_K1 : FA_OFF_K0);
        const float* Kg = qb + EE + (long)(kt*64)*E3;
        #pragma unroll
        for (int p = 0; p < 8; p++) {
            int idx = p*256 + tid;
            int r = idx >> 5, c4 = (idx & 31) << 2;
            CP_ASYNC16(smem_u32(Kd + r*FQ_LD + c4), Kg + (long)r*E3 + c4);
        }
    };
    auto issueV = [&](int kt) {
        const float* Vg = qb + 2*EE + (long)(kt*64)*E3;
        #pragma unroll
        for (int p = 0; p < 8; p++) {
            int idx = p*256 + tid;
            int r = idx >> 5, c4 = (idx & 31) << 2;
            CP_ASYNC16(smem_u32(Vu + r*FV_LD + c4), Vg + (long)r*E3 + c4);
        }
    };

    {
        const float* Qg = qb + (long)(qt*128)*E3;
        #pragma unroll
        for (int p = 0; p < 16; p++) {
            int idx = p*256 + tid;
            int r = idx >> 5, c4 = (idx & 31) << 2;
            CP_ASYNC16(smem_u32(Qs + r*FQ_LD + c4), Qg + (long)r*E3 + c4);
        }
    }
    issueK(0); issueV(0); CP_COMMIT();

    float o[16][4];
    #pragma unroll
    for (int nt = 0; nt < 16; nt++)
        #pragma unroll
        for (int r = 0; r < 4; r++) o[nt][r] = 0.f;
    float m0 = -1e30f, m1 = -1e30f, l0 = 0.f, l1 = 0.f;

    int rowg0 = qt*128 + wid*16 + gq;
    int rowg1 = rowg0 + 8;
    int nkt = 2*(qt + 1);

    for (int kt = 0; kt < nkt; kt++) {
        CP_WAIT(0);
        __syncthreads();
        if (kt + 1 < nkt) { issueK(kt + 1); CP_COMMIT(); }

        uint32_t kb_base = smbase
            + (uint32_t)(((kt & 1) ? FA_OFF_K1 : FA_OFF_K0) * 4) + kb_off;

        // ---- S = Q K^T via ldmatrix ----
        float s[8][4];
        #pragma unroll
        for (int nt = 0; nt < 8; nt++)
            #pragma unroll
            for (int r = 0; r < 4; r++) s[nt][r] = 0.f;

        #pragma unroll
        for (int ks = 0; ks < 16; ks++) {
            uint32_t kc4 = ks * 32;
            uint32_t a[4], bmat[4][4];
            ldsm4(a, qa_base + kc4);
            #pragma unroll
            for (int np = 0; np < 4; np++)
                ldsm4(bmat[np], kb_base + np*(16*FQ_LD*4) + kc4);
            #pragma unroll
            for (int np = 0; np < 4; np++) {
                mma8(s[2*np],   a, &bmat[np][0]);
                mma8(s[2*np+1], a, &bmat[np][2]);
            }
        }

        // ---- causal mask ----
        if (kt >= 2*qt) {
            #pragma unroll
            for (int nt = 0; nt < 8; nt++) {
                int col = kt*64 + nt*8 + 2*tg;
                if (col   > rowg0) s[nt][0] = -1e30f;
                if (col+1 > rowg0) s[nt][1] = -1e30f;
                if (col   > rowg1) s[nt][2] = -1e30f;
                if (col+1 > rowg1) s[nt][3] = -1e30f;
            }
        }

        // ---- online softmax ----
        float mt0 = -1e30f, mt1 = -1e30f;
        #pragma unroll
        for (int nt = 0; nt < 8; nt++) {
            mt0 = fmaxf(mt0, fmaxf(s[nt][0], s[nt][1]));
            mt1 = fmaxf(mt1, fmaxf(s[nt][2], s[nt][3]));
        }
        mt0 = fmaxf(mt0, __shfl_xor_sync(0xffffffffu, mt0, 1));
        mt0 = fmaxf(mt0, __shfl_xor_sync(0xffffffffu, mt0, 2));
        mt1 = fmaxf(mt1, __shfl_xor_sync(0xffffffffu, mt1, 1));
        mt1 = fmaxf(mt1, __shfl_xor_sync(0xffffffffu, mt1, 2));

        float mn0 = fmaxf(m0, mt0), mn1 = fmaxf(m1, mt1);
        float c0 = __expf(m0 - mn0), c1 = __expf(m1 - mn1);

        float sum0 = 0.f, sum1 = 0.f;
        #pragma unroll
        for (int nt = 0; nt < 8; nt++) {
            s[nt][0] = __expf(s[nt][0] - mn0);
            s[nt][1] = __expf(s[nt][1] - mn0);
            s[nt][2] = __expf(s[nt][2] - mn1);
            s[nt][3] = __expf(s[nt][3] - mn1);
            sum0 += s[nt][0] + s[nt][1];
            sum1 += s[nt][2] + s[nt][3];
        }
        sum0 += __shfl_xor_sync(0xffffffffu, sum0, 1);
        sum0 += __shfl_xor_sync(0xffffffffu, sum0, 2);
        sum1 += __shfl_xor_sync(0xffffffffu, sum1, 1);
        sum1 += __shfl_xor_sync(0xffffffffu, sum1, 2);

        l0 = l0*c0 + sum0;  l1 = l1*c1 + sum1;
        m0 = mn0;           m1 = mn1;

        #pragma unroll
        for (int nt = 0; nt < 16; nt++) {
            o[nt][0] *= c0; o[nt][1] *= c0;
            o[nt][2] *= c1; o[nt][3] *= c1;
        }

        // ---- P (tf32) -> warp-private smem ----
        #pragma unroll
        for (int nt = 0; nt < 8; nt++) {
            int cb = nt*8 + 2*tg;
            uint2 v0 = make_uint2(f2tf(s[nt][0]), f2tf(s[nt][1]));
            uint2 v1 = make_uint2(f2tf(s[nt][2]), f2tf(s[nt][3]));
            *(uint2*)&Ps[(wid*16 + gq    )*FP_LD + cb] = v0;
            *(uint2*)&Ps[(wid*16 + gq + 8)*FP_LD + cb] = v1;
        }
        __syncwarp();

        // ---- O += P @ V (P via ldmatrix, V scalar) ----
        #pragma unroll
        for (int ks = 0; ks < 8; ks++) {
            int kc = ks*8;
            uint32_t a[4];
            ldsm4(a, pa_base + (uint32_t)(kc*4));
            #pragma unroll
            for (int nt = 0; nt < 16; nt++) {
                const uint32_t* pv = Vu + (kc + tg)*FV_LD + nt*8 + gq;
                uint32_t bb[2] = { pv[0], pv[4*FV_LD] };
                mma8(o[nt], a, bb);
            }
        }
        __syncthreads();
        if (kt + 1 < nkt) { issueV(kt + 1); CP_COMMIT(); }
    }

    // ---- normalize + tf32-round + store (out-proj reads raw fragments) ----
    float i0 = 1.f/l0, i1 = 1.f/l1;
    float* cb0 = ctx + (long)b*SS*EE + (long)rowg0*EE + h*DD;
    float* cb1 = cb0 + 8*EE;
    #pragma unroll
    for (int nt = 0; nt < 16; nt++) {
        int col = nt*8 + 2*tg;
        float2 v0 = make_float2(tfround(o[nt][0]*i0), tfround(o[nt][1]*i0));
        float2 v1 = make_float2(tfround(o[nt][2]*i1), tfround(o[nt][3]*i1));
        *(float2*)(cb0 + col) = v0;
        *(float2*)(cb1 + col) = v1;
    }
}

// ---------------------------------------------------------------------------
// RoPE in-place on q,k; pre-scales q by 1/sqrt(D), rounds q,k,v to tf32.
// ---------------------------------------------------------------------------
__global__ __launch_bounds__(256)
void rope_k(float* __restrict__ qkv)
{
    long t = (long)blockIdx.x * blockDim.x + threadIdx.x;
    int j = (int)(t & 63);
    int h = (int)((t >> 6) & (HH_-1));
    long bs = t >> 10;
    int s = (int)(bs & (SS-1));

    const float scale = 0.08838834764831845f;  // 1/sqrt(128)
    float inv = powf(10000.f, -((float)(2*j)) * (1.f/128.f));
    float fr  = (float)s * inv;
    float c, sn;
    sincosf(fr, &sn, &c);

    float* q = qkv + bs*(long)E3 + (long)h*DD;
    float q1 = q[j], q2 = q[j+64];
    q[j]    = tfround((q1*c - q2*sn) * scale);
    q[j+64] = tfround((q1*sn + q2*c) * scale);

    float* k = q + EE;
    float k1 = k[j], k2 = k[j+64];
    k[j]    = tfround(k1*c - k2*sn);
    k[j+64] = tfround(k1*sn + k2*c);

    float* v = k + EE;
    v[j]    = tfround(v[j]);
    v[j+64] = tfround(v[j+64]);
}

// ---------------------------------------------------------------------------
extern "C" void kernel_launch(void* const* d_in, const int* in_sizes, int n_in,
                              void* d_out, int out_size)
{
    const float* x      = (const float*)d_in[0];
    const float* wqkv_w = (const float*)d_in[1];
    const float* wqkv_b = (const float*)d_in[2];
    const float* out_w  = (const float*)d_in[3];
    const float* out_b  = (const float*)d_in[4];
    float*       out    = (float*)d_out;

    float *qkv, *ctx, *xr, *w1r, *w2r;
    cudaGetSymbolAddress((void**)&qkv, g_qkv);
    cudaGetSymbolAddress((void**)&ctx, g_ctx);
    cudaGetSymbolAddress((void**)&xr,  g_xr);
    cudaGetSymbolAddress((void**)&w1r, g_w1r);
    cudaGetSymbolAddress((void**)&w2r, g_w2r);

    cudaFuncSetAttribute(tgemm2<true>, cudaFuncAttributeMaxDynamicSharedMemorySize, SMEM2);
    cudaFuncSetAttribute(fa_k,         cudaFuncAttributeMaxDynamicSharedMemorySize, FA_SMEM);

    const int Mx = BB*SS;             // 4096

    // 0) tf32 round-copies (inputs of the two projections)
    tfcopy_k<<<(unsigned)(((long)Mx*EE)/1024), 256>>>(x, xr);
    tfcopy_k<<<(unsigned)(((long)E3*EE)/1024), 256>>>(wqkv_w, w1r);
    tfcopy_k<<<(unsigned)(((long)EE*EE)/1024), 256>>>(out_w, w2r);

    // 1) QKV projection
    {
        dim3 g(E3/BN2, Mx/BM2, 1);
        tgemm2<true><<<g,256,SMEM2>>>(xr, w1r, qkv, wqkv_b, EE, EE, EE, E3);
    }
    // 2) RoPE + tf32 pre-round + q pre-scale
    {
        long total = (long)BB*SS*HH_*64;
        rope_k<<<(unsigned)(total/256), 256>>>(qkv);
    }
    // 3) fused flash attention -> ctx (tf32-rounded)
    {
        dim3 g(SS/128, BB*HH_);
        fa_k<<<g,256,FA_SMEM>>>(qkv, ctx);
    }
    // 4) output projection
    {
        dim3 g(EE/BN2, Mx/BM2, 1);
        tgemm2<true><<<g,256,SMEM2>>>(ctx, w2r, out, out_b, EE, EE, EE, EE);
    }
}

// round 8
// speedup vs baseline: 1.9499x; 1.8173x over previous
#include <cuda_runtime.h>
#include <cuda_fp16.h>
#include <math.h>
#include <cstdint>

// Problem constants
#define BB 2
#define SS 2048
#define EE 2048
#define HH_ 16
#define DD 128
#define E3 (3*EE)

// Scratch (allocation-free rule: __device__ globals)
__device__ float  g_qkv [(long)BB*SS*E3];   // fp32 qkv (gemm out, rope in)
__device__ __half g_qkvh[(long)BB*SS*E3];   // half qkv (rope out, FA in)
__device__ __half g_ctxh[(long)BB*SS*EE];   // half ctx (FA out, out-proj in)
__device__ __half g_xh [(long)BB*SS*EE];
__device__ __half g_w1h[(long)E3*EE];
__device__ __half g_w2h[(long)EE*EE];

__device__ __forceinline__ void mma16(float* d, const uint32_t* a, const uint32_t* b) {
    asm volatile("mma.sync.aligned.m16n8k16.row.col.f32.f16.f16.f32 "
        "{%0,%1,%2,%3}, {%4,%5,%6,%7}, {%8,%9}, {%0,%1,%2,%3};"
        : "+f"(d[0]), "+f"(d[1]), "+f"(d[2]), "+f"(d[3])
        : "r"(a[0]), "r"(a[1]), "r"(a[2]), "r"(a[3]), "r"(b[0]), "r"(b[1]));
}
__device__ __forceinline__ void ldsm4(uint32_t* r, uint32_t addr) {
    asm volatile("ldmatrix.sync.aligned.m8n8.x4.shared.b16 {%0,%1,%2,%3}, [%4];"
        : "=r"(r[0]), "=r"(r[1]), "=r"(r[2]), "=r"(r[3]) : "r"(addr));
}
__device__ __forceinline__ void ldsm4t(uint32_t* r, uint32_t addr) {
    asm volatile("ldmatrix.sync.aligned.m8n8.x4.trans.shared.b16 {%0,%1,%2,%3}, [%4];"
        : "=r"(r[0]), "=r"(r[1]), "=r"(r[2]), "=r"(r[3]) : "r"(addr));
}
__device__ __forceinline__ uint32_t smem_u32(const void* p) {
    uint32_t a;
    asm("{ .reg .u64 t; cvta.to.shared.u64 t, %1; cvt.u32.u64 %0, t; }"
        : "=r"(a) : "l"(p));
    return a;
}
#define CP_ASYNC16(dst, src) \
    asm volatile("cp.async.ca.shared.global [%0], [%1], 16;" :: "r"(dst), "l"(src))
#define CP_COMMIT() asm volatile("cp.async.commit_group;" ::: "memory")
#define CP_WAIT(n)  asm volatile("cp.async.wait_group %0;" :: "n"(n) : "memory")

// ---------------------------------------------------------------------------
// fp32 -> fp16 round-copy (8 floats / thread)
// ---------------------------------------------------------------------------
__global__ __launch_bounds__(256)
void h16copy_k(const float* __restrict__ in, __half* __restrict__ out)
{
    long i = ((long)blockIdx.x*256 + threadIdx.x) * 8;
    float4 v0 = *(const float4*)(in + i);
    float4 v1 = *(const float4*)(in + i + 4);
    __half2 h0 = __floats2half2_rn(v0.x, v0.y);
    __half2 h1 = __floats2half2_rn(v0.z, v0.w);
    __half2 h2 = __floats2half2_rn(v1.x, v1.y);
    __half2 h3 = __floats2half2_rn(v1.z, v1.w);
    uint4 o;
    o.x = *(uint32_t*)&h0; o.y = *(uint32_t*)&h1;
    o.z = *(uint32_t*)&h2; o.w = *(uint32_t*)&h3;
    *(uint4*)(out + i) = o;
}

// ===========================================================================
// fp16 pipelined GEMM (TRANSB): C[m,n]= sum_k A[m,k]*B[n,k] (+bias), fp32 out
// CTA 128x256, 8 warps (2x4), warp 64x64, BK=64 halves, 3-stage cp.async,
// ldmatrix fragments, m16n8k16.
// ===========================================================================
#define BM2 128
#define BN2 256
#define BKH 64
#define LDH 72                      // halves; 144B row stride -> 4-bank shift
#define A_ST_H (128*LDH)            // 9216 halves
#define B_ST_H (256*LDH)            // 18432 halves
#define ST_H (A_ST_H + B_ST_H)      // 27648 halves / stage
#define SMEM2 (3*ST_H*2)            // 165888 bytes

template<bool BIAS>
__global__ __launch_bounds__(256)
void tgemm2h(const __half* __restrict__ gA, const __half* __restrict__ gB,
             float* __restrict__ gC, const float* __restrict__ bias,
             int K, int lda, int ldb, int ldc)
{
    extern __shared__ __half smh[];
    int m0 = blockIdx.y * BM2;
    int n0 = blockIdx.x * BN2;
    int niter = K / BKH;

    int tid  = threadIdx.x;
    int wid  = tid >> 5;
    int lane = tid & 31;
    int wm = wid & 1;
    int wn = wid >> 1;
    int gq = lane >> 2;
    int tg = lane & 3;

    // ldmatrix lane offsets (halves)
    int a_row = (lane & 7) + ((lane >> 3) & 1) * 8;
    int a_col = (lane >> 4) * 8;
    int b_row = (lane & 7) + (lane >> 4) * 8;
    int b_col = ((lane >> 3) & 1) * 8;
    uint32_t smbase = smem_u32(smh);
    uint32_t aoff = ((wm*64 + a_row) * LDH + a_col) * 2;
    uint32_t boff = (uint32_t)(A_ST_H*2) + ((wn*64 + b_row) * LDH + b_col) * 2;

    float acc[4][8][4];
    #pragma unroll
    for (int mt = 0; mt < 4; mt++)
        #pragma unroll
        for (int nt = 0; nt < 8; nt++)
            #pragma unroll
            for (int r = 0; r < 4; r++) acc[mt][nt][r] = 0.f;

    auto issue = [&](int it) {
        int k0 = it * BKH;
        __half* As = smh + (it % 3) * ST_H;
        __half* Bs = As + A_ST_H;
        const __half* Ab = gA + (long)m0 * lda + k0;
        #pragma unroll
        for (int p = 0; p < 4; p++) {        // 128 rows x 8 chunks
            int idx = p * 256 + tid;
            int r = idx >> 3, c8 = (idx & 7) << 3;
            CP_ASYNC16(smem_u32(As + r * LDH + c8), Ab + (long)r * lda + c8);
        }
        const __half* Bb = gB + (long)n0 * ldb + k0;
        #pragma unroll
        for (int p = 0; p < 8; p++) {        // 256 rows x 8 chunks
            int idx = p * 256 + tid;
            int r = idx >> 3, c8 = (idx & 7) << 3;
            CP_ASYNC16(smem_u32(Bs + r * LDH + c8), Bb + (long)r * ldb + c8);
        }
        CP_COMMIT();
    };

    auto compute = [&](int s) {
        uint32_t a_base = smbase + s*(ST_H*2) + aoff;
        uint32_t b_base = smbase + s*(ST_H*2) + boff;
        #pragma unroll
        for (int ks = 0; ks < 4; ks++) {     // 4 x k16
            uint32_t kcb = ks * 32;          // 16 halves = 32 bytes
            uint32_t a[4][4], b[4][4];
            #pragma unroll
            for (int mt = 0; mt < 4; mt++)
                ldsm4(a[mt], a_base + mt*(16*LDH*2) + kcb);
            #pragma unroll
            for (int np = 0; np < 4; np++)
                ldsm4(b[np], b_base + np*(16*LDH*2) + kcb);
            #pragma unroll
            for (int mt = 0; mt < 4; mt++)
                #pragma unroll
                for (int np = 0; np < 4; np++) {
                    mma16(acc[mt][2*np],   a[mt], &b[np][0]);
                    mma16(acc[mt][2*np+1], a[mt], &b[np][2]);
                }
        }
    };

    issue(0);
    if (niter > 1) issue(1);
    for (int it = 0; it < niter; ++it) {
        if (it + 1 < niter) CP_WAIT(1); else CP_WAIT(0);
        __syncthreads();
        if (it + 2 < niter) issue(it + 2);
        compute(it % 3);
    }

    #pragma unroll
    for (int mt = 0; mt < 4; mt++) {
        int row = m0 + wm*64 + mt*16 + gq;
        #pragma unroll
        for (int nt = 0; nt < 8; nt++) {
            int col = n0 + wn*64 + nt*8 + 2*tg;
            float b0 = 0.f, b1 = 0.f;
            if (BIAS) { b0 = bias[col]; b1 = bias[col + 1]; }
            float2 v0, v1;
            v0.x = acc[mt][nt][0] + b0; v0.y = acc[mt][nt][1] + b1;
            v1.x = acc[mt][nt][2] + b0; v1.y = acc[mt][nt][3] + b1;
            *(float2*)(gC + (long)row * ldc + col)       = v0;
            *(float2*)(gC + (long)(row + 8) * ldc + col) = v1;
        }
    }
}

// ===========================================================================
// fp16 flash attention. Per CTA: one 128-row q-tile of one (b,h).
// Smem halves: Q[128][136] | K0[64][136] | K1[64][136] | V[64][136] | P[128][72]
//            = 52736 halves = 105472 bytes
// ===========================================================================
#define FQ_LDH 136
#define FP_LDH 72
#define FA_K0_H (128*FQ_LDH)
#define FA_K1_H (FA_K0_H + 64*FQ_LDH)
#define FA_V_H  (FA_K1_H + 64*FQ_LDH)
#define FA_P_H  (FA_V_H  + 64*FQ_LDH)
#define FA_SMEM ((FA_P_H + 128*FP_LDH)*2)

__global__ __launch_bounds__(256)
void fa_k(const __half* __restrict__ qkv, __half* __restrict__ ctx)
{
    extern __shared__ __half smh[];
    __half* Qs = smh;
    __half* Vs = smh + FA_V_H;
    __half* Ps = smh + FA_P_H;

    int qt = gridDim.x - 1 - blockIdx.x;       // heavy tiles first
    int bh = blockIdx.y;
    int b = bh >> 4, h = bh & 15;
    const __half* qb = qkv + (long)b*SS*E3 + (long)h*DD;

    int tid = threadIdx.x, wid = tid >> 5, lane = tid & 31;
    int gq = lane >> 2, tg = lane & 3;

    int a_row = (lane & 7) + ((lane >> 3) & 1) * 8;
    int a_col = (lane >> 4) * 8;               // halves
    int b_row = (lane & 7) + (lane >> 4) * 8;
    int b_col = ((lane >> 3) & 1) * 8;
    uint32_t smbase = smem_u32(smh);
    uint32_t qa_base = smbase + ((wid*16 + a_row)*FQ_LDH + a_col) * 2;
    uint32_t kb_off  = (b_row*FQ_LDH + b_col) * 2;
    uint32_t pa_base = smbase + (uint32_t)(FA_P_H*2)
                     + ((wid*16 + a_row)*FP_LDH + a_col) * 2;
    uint32_t va_off  = (uint32_t)(FA_V_H*2) + (a_row*FQ_LDH + a_col) * 2;

    auto issueK = [&](int kt) {
        __half* Kd = smh + ((kt & 1) ? FA_K1_H : FA_K0_H);
        const __half* Kg = qb + EE + (long)(kt*64)*E3;
        #pragma unroll
        for (int p = 0; p < 4; p++) {          // 64 rows x 16 chunks
            int idx = p*256 + tid;
            int r = idx >> 4, c8 = (idx & 15) << 3;
            CP_ASYNC16(smem_u32(Kd + r*FQ_LDH + c8), Kg + (long)r*E3 + c8);
        }
    };
    auto issueV = [&](int kt) {
        const __half* Vg = qb + 2*EE + (long)(kt*64)*E3;
        #pragma unroll
        for (int p = 0; p < 4; p++) {
            int idx = p*256 + tid;
            int r = idx >> 4, c8 = (idx & 15) << 3;
            CP_ASYNC16(smem_u32(Vs + r*FQ_LDH + c8), Vg + (long)r*E3 + c8);
        }
    };

    {   // Q tile 128 x 128 halves
        const __half* Qg = qb + (long)(qt*128)*E3;
        #pragma unroll
        for (int p = 0; p < 8; p++) {
            int idx = p*256 + tid;
            int r = idx >> 4, c8 = (idx & 15) << 3;
            CP_ASYNC16(smem_u32(Qs + r*FQ_LDH + c8), Qg + (long)r*E3 + c8);
        }
    }
    issueK(0); issueV(0); CP_COMMIT();

    float o[16][4];
    #pragma unroll
    for (int nt = 0; nt < 16; nt++)
        #pragma unroll
        for (int r = 0; r < 4; r++) o[nt][r] = 0.f;
    float m0 = -1e30f, m1 = -1e30f, l0 = 0.f, l1 = 0.f;

    int rowg0 = qt*128 + wid*16 + gq;
    int rowg1 = rowg0 + 8;
    int nkt = 2*(qt + 1);

    for (int kt = 0; kt < nkt; kt++) {
        CP_WAIT(0);
        __syncthreads();
        if (kt + 1 < nkt) { issueK(kt + 1); CP_COMMIT(); }

        uint32_t kb_base = smbase
            + (uint32_t)(((kt & 1) ? FA_K1_H : FA_K0_H) * 2) + kb_off;

        // ---- S = Q K^T (16 rows x 64 cols / warp) ----
        float s[8][4];
        #pragma unroll
        for (int nt = 0; nt < 8; nt++)
            #pragma unroll
            for (int r = 0; r < 4; r++) s[nt][r] = 0.f;

        #pragma unroll
        for (int ks = 0; ks < 8; ks++) {       // D=128 / k16
            uint32_t kcb = ks * 32;
            uint32_t a[4], bm[4][4];
            ldsm4(a, qa_base + kcb);
            #pragma unroll
            for (int np = 0; np < 4; np++)
                ldsm4(bm[np], kb_base + np*(16*FQ_LDH*2) + kcb);
            #pragma unroll
            for (int np = 0; np < 4; np++) {
                mma16(s[2*np],   a, &bm[np][0]);
                mma16(s[2*np+1], a, &bm[np][2]);
            }
        }

        // ---- causal mask (q pre-scaled) ----
        if (kt >= 2*qt) {
            #pragma unroll
            for (int nt = 0; nt < 8; nt++) {
                int col = kt*64 + nt*8 + 2*tg;
                if (col   > rowg0) s[nt][0] = -1e30f;
                if (col+1 > rowg0) s[nt][1] = -1e30f;
                if (col   > rowg1) s[nt][2] = -1e30f;
                if (col+1 > rowg1) s[nt][3] = -1e30f;
            }
        }

        // ---- online softmax (fp32) ----
        float mt0 = -1e30f, mt1 = -1e30f;
        #pragma unroll
        for (int nt = 0; nt < 8; nt++) {
            mt0 = fmaxf(mt0, fmaxf(s[nt][0], s[nt][1]));
            mt1 = fmaxf(mt1, fmaxf(s[nt][2], s[nt][3]));
        }
        mt0 = fmaxf(mt0, __shfl_xor_sync(0xffffffffu, mt0, 1));
        mt0 = fmaxf(mt0, __shfl_xor_sync(0xffffffffu, mt0, 2));
        mt1 = fmaxf(mt1, __shfl_xor_sync(0xffffffffu, mt1, 1));
        mt1 = fmaxf(mt1, __shfl_xor_sync(0xffffffffu, mt1, 2));

        float mn0 = fmaxf(m0, mt0), mn1 = fmaxf(m1, mt1);
        float c0 = __expf(m0 - mn0), c1 = __expf(m1 - mn1);

        float sum0 = 0.f, sum1 = 0.f;
        #pragma unroll
        for (int nt = 0; nt < 8; nt++) {
            s[nt][0] = __expf(s[nt][0] - mn0);
            s[nt][1] = __expf(s[nt][1] - mn0);
            s[nt][2] = __expf(s[nt][2] - mn1);
            s[nt][3] = __expf(s[nt][3] - mn1);
            sum0 += s[nt][0] + s[nt][1];
            sum1 += s[nt][2] + s[nt][3];
        }
        sum0 += __shfl_xor_sync(0xffffffffu, sum0, 1);
        sum0 += __shfl_xor_sync(0xffffffffu, sum0, 2);
        sum1 += __shfl_xor_sync(0xffffffffu, sum1, 1);
        sum1 += __shfl_xor_sync(0xffffffffu, sum1, 2);

        l0 = l0*c0 + sum0;  l1 = l1*c1 + sum1;
        m0 = mn0;           m1 = mn1;

        #pragma unroll
        for (int nt = 0; nt < 16; nt++) {
            o[nt][0] *= c0; o[nt][1] *= c0;
            o[nt][2] *= c1; o[nt][3] *= c1;
        }

        // ---- P (half) -> warp-private smem ----
        #pragma unroll
        for (int nt = 0; nt < 8; nt++) {
            int cb = nt*8 + 2*tg;
            __half2 h0 = __floats2half2_rn(s[nt][0], s[nt][1]);
            __half2 h1 = __floats2half2_rn(s[nt][2], s[nt][3]);
            *(__half2*)&Ps[(wid*16 + gq    )*FP_LDH + cb] = h0;
            *(__half2*)&Ps[(wid*16 + gq + 8)*FP_LDH + cb] = h1;
        }
        __syncwarp();

        // ---- O += P @ V (P ldmatrix, V ldmatrix.trans) ----
        #pragma unroll
        for (int ks = 0; ks < 4; ks++) {       // 64 k / k16
            uint32_t a[4];
            ldsm4(a, pa_base + ks*32);
            uint32_t v_base = smbase + va_off + (uint32_t)(ks*16*FQ_LDH*2);
            #pragma unroll
            for (int np = 0; np < 8; np++) {   // 128 n / n16
                uint32_t vb[4];
                ldsm4t(vb, v_base + np*32);    // 16 halves = 32B per n16
                mma16(o[2*np],   a, &vb[0]);
                mma16(o[2*np+1], a, &vb[2]);
            }
        }
        __syncthreads();
        if (kt + 1 < nkt) { issueV(kt + 1); CP_COMMIT(); }
    }

    // ---- normalize + store half ctx ----
    float i0 = 1.f/l0, i1 = 1.f/l1;
    __half* cb0 = ctx + (long)b*SS*EE + (long)rowg0*EE + h*DD;
    __half* cb1 = cb0 + 8*EE;
    #pragma unroll
    for (int nt = 0; nt < 16; nt++) {
        int col = nt*8 + 2*tg;
        __half2 v0 = __floats2half2_rn(o[nt][0]*i0, o[nt][1]*i0);
        __half2 v1 = __floats2half2_rn(o[nt][2]*i1, o[nt][3]*i1);
        *(__half2*)(cb0 + col) = v0;
        *(__half2*)(cb1 + col) = v1;
    }
}

// ---------------------------------------------------------------------------
// RoPE: reads fp32 qkv, applies rotation (q pre-scaled by 1/sqrt(D)),
// writes half qkvh (q,k rotated; v converted).
// ---------------------------------------------------------------------------
__global__ __launch_bounds__(256)
void rope_k(const float* __restrict__ qkv, __half* __restrict__ qkvh)
{
    long t = (long)blockIdx.x * blockDim.x + threadIdx.x;
    int j = (int)(t & 63);
    int h = (int)((t >> 6) & (HH_-1));
    long bs = t >> 10;
    int s = (int)(bs & (SS-1));

    const float scale = 0.08838834764831845f;  // 1/sqrt(128)
    float inv = powf(10000.f, -((float)(2*j)) * (1.f/128.f));
    float fr  = (float)s * inv;
    float c, sn;
    sincosf(fr, &sn, &c);

    const float* q = qkv + bs*(long)E3 + (long)h*DD;
    __half* qh = qkvh + bs*(long)E3 + (long)h*DD;
    float q1 = q[j], q2 = q[j+64];
    qh[j]    = __float2half_rn((q1*c - q2*sn) * scale);
    qh[j+64] = __float2half_rn((q1*sn + q2*c) * scale);

    const float* k = q + EE;
    __half* kh = qh + EE;
    float k1 = k[j], k2 = k[j+64];
    kh[j]    = __float2half_rn(k1*c - k2*sn);
    kh[j+64] = __float2half_rn(k1*sn + k2*c);

    const float* v = k + EE;
    __half* vh = kh + EE;
    vh[j]    = __float2half_rn(v[j]);
    vh[j+64] = __float2half_rn(v[j+64]);
}

// ---------------------------------------------------------------------------
extern "C" void kernel_launch(void* const* d_in, const int* in_sizes, int n_in,
                              void* d_out, int out_size)
{
    const float* x      = (const float*)d_in[0];
    const float* wqkv_w = (const float*)d_in[1];
    const float* wqkv_b = (const float*)d_in[2];
    const float* out_w  = (const float*)d_in[3];
    const float* out_b  = (const float*)d_in[4];
    float*       out    = (float*)d_out;

    float *qkv;
    __half *qkvh, *ctxh, *xh, *w1h, *w2h;
    cudaGetSymbolAddress((void**)&qkv,  g_qkv);
    cudaGetSymbolAddress((void**)&qkvh, g_qkvh);
    cudaGetSymbolAddress((void**)&ctxh, g_ctxh);
    cudaGetSymbolAddress((void**)&xh,   g_xh);
    cudaGetSymbolAddress((void**)&w1h,  g_w1h);
    cudaGetSymbolAddress((void**)&w2h,  g_w2h);

    cudaFuncSetAttribute(tgemm2h<true>, cudaFuncAttributeMaxDynamicSharedMemorySize, SMEM2);
    cudaFuncSetAttribute(fa_k,          cudaFuncAttributeMaxDynamicSharedMemorySize, FA_SMEM);

    const int Mx = BB*SS;             // 4096

    // 0) fp16 copies of GEMM inputs
    h16copy_k<<<(unsigned)(((long)Mx*EE)/2048), 256>>>(x, xh);
    h16copy_k<<<(unsigned)(((long)E3*EE)/2048), 256>>>(wqkv_w, w1h);
    h16copy_k<<<(unsigned)(((long)EE*EE)/2048), 256>>>(out_w, w2h);

    // 1) QKV projection (fp16 in, fp32 out + bias)
    {
        dim3 g(E3/BN2, Mx/BM2, 1);
        tgemm2h<true><<<g,256,SMEM2>>>(xh, w1h, qkv, wqkv_b, EE, EE, EE, E3);
    }
    // 2) RoPE fp32 -> half qkvh (q pre-scaled)
    {
        long total = (long)BB*SS*HH_*64;
        rope_k<<<(unsigned)(total/256), 256>>>(qkv, qkvh);
    }
    // 3) fused flash attention -> half ctx
    {
        dim3 g(SS/128, BB*HH_);
        fa_k<<<g,256,FA_SMEM>>>(qkvh, ctxh);
    }
    // 4) output projection (fp16 in, fp32 out + bias)
    {
        dim3 g(EE/BN2, Mx/BM2, 1);
        tgemm2h<true><<<g,256,SMEM2>>>(ctxh, w2h, out, out_b, EE, EE, EE, EE);
    }
}